// round 3
// baseline (speedup 1.0000x reference)
#include <cuda_runtime.h>
#include <cuda_bf16.h>
#include <cstdint>

// Problem constants (fixed by the dataset)
#define NE 50000
#define NR 2000
#define EMAX 800000
#define NHEAD 8
#define DIM 128
#define NEG_SLOPE 0.01f
#define NSEG (2 * NE)
#define TILE 512
#define NTILES ((NSEG + TILE - 1) / TILE)   // 196

// ---------------- scratch (static device globals; no allocation) -------------
__device__ float g_ph[NE * NHEAD];      // x_e @ Wh.T
__device__ float g_pt[NE * NHEAD];      // x_e @ Wt.T
__device__ float g_pr[NR * NHEAD];      // x_r @ Wr.T
__device__ int   g_deg[NSEG];           // degrees: [0,NE)=h side, [NE,2NE)=t side
__device__ int   g_coffs[NSEG + 1];     // exclusive offsets (combined h|t CSR)
__device__ int   g_cur[NSEG];           // scatter cursors
__device__ int   g_elist[2 * EMAX];     // rel id per slot, grouped by (side,node)
__device__ int2  g_ht[EMAX];            // decoded (h, t) per edge
__device__ int   g_rel32[EMAX];         // rel cast to int32
__device__ int   g_tsum[NTILES];        // per-tile degree sums
__device__ int   g_toff[NTILES];        // per-tile exclusive offsets
__device__ int   g_is64;                // 1 if edge_index/rel are int64

__device__ __forceinline__ float lrelu(float s) {
    return (s > 0.0f) ? s : NEG_SLOPE * s;
}

// ---------------- kernel 0: zero degrees + detect index width ----------------
__global__ void k_zero_detect(const unsigned* ei_words) {
    int i = blockIdx.x * blockDim.x + threadIdx.x;
    if (i < NSEG) g_deg[i] = 0;
    if (blockIdx.x == 0 && threadIdx.x < 32) {
        unsigned w = ei_words[2 * threadIdx.x + 1];
        unsigned ball = __ballot_sync(0xffffffffu, w == 0u);
        if (threadIdx.x == 0) g_is64 = (ball == 0xffffffffu) ? 1 : 0;
    }
}

// ---------------- kernel 1: projections (warp per row) -----------------------
__global__ __launch_bounds__(256) void k_proj(const float* __restrict__ x,
                                              const float* __restrict__ Wa,
                                              const float* __restrict__ Wb,
                                              int n, int mode) {
    int w = (blockIdx.x * blockDim.x + threadIdx.x) >> 5;
    int lane = threadIdx.x & 31;
    if (w >= n) return;
    float* pa = (mode == 0) ? g_ph : g_pr;
    float* pb = (mode == 0) ? g_pt : nullptr;

    const float* xr = x + (long)w * DIM;
    float x0 = xr[lane], x1 = xr[lane + 32], x2 = xr[lane + 64], x3 = xr[lane + 96];

#pragma unroll
    for (int h = 0; h < NHEAD; h++) {
        const float* wa = Wa + h * DIM;
        float a = x0 * wa[lane] + x1 * wa[lane + 32] + x2 * wa[lane + 64] + x3 * wa[lane + 96];
#pragma unroll
        for (int off = 16; off > 0; off >>= 1) a += __shfl_xor_sync(0xffffffffu, a, off);
        if (lane == 0) pa[w * NHEAD + h] = a;
        if (pb) {
            const float* wb = Wb + h * DIM;
            float b = x0 * wb[lane] + x1 * wb[lane + 32] + x2 * wb[lane + 64] + x3 * wb[lane + 96];
#pragma unroll
            for (int off = 16; off > 0; off >>= 1) b += __shfl_xor_sync(0xffffffffu, b, off);
            if (lane == 0) pb[w * NHEAD + h] = b;
        }
    }
}

// ---------------- kernel 2: decode + degree histogram (4 edges/thread) -------
__global__ __launch_bounds__(256) void k_hist(const void* __restrict__ ei,
                                              const void* __restrict__ rel, int E) {
    int e0 = (blockIdx.x * blockDim.x + threadIdx.x) * 4;
    if (e0 >= E) return;
    int is64 = g_is64;
    int h[4], t[4], r[4];
#pragma unroll
    for (int k = 0; k < 4; k++) {
        int e = e0 + k;
        if (e < E) {
            if (is64) {
                h[k] = (int)((const long long*)ei)[e];
                t[k] = (int)((const long long*)ei)[(long)E + e];
                r[k] = (int)((const long long*)rel)[e];
            } else {
                h[k] = ((const int*)ei)[e];
                t[k] = ((const int*)ei)[(long)E + e];
                r[k] = ((const int*)rel)[e];
            }
        }
    }
#pragma unroll
    for (int k = 0; k < 4; k++) {
        int e = e0 + k;
        if (e < E) {
            g_ht[e] = make_int2(h[k], t[k]);
            g_rel32[e] = r[k];
            atomicAdd(&g_deg[h[k]], 1);
            atomicAdd(&g_deg[NE + t[k]], 1);
        }
    }
}

// ---------------- kernels 3a/3b/3c: parallel exclusive scan ------------------
__global__ __launch_bounds__(256) void k_scan_a() {
    __shared__ int sh[256];
    int tid = threadIdx.x;
    int i0 = blockIdx.x * TILE + tid * 2;
    int v = 0;
    if (i0 < NSEG) v += g_deg[i0];
    if (i0 + 1 < NSEG) v += g_deg[i0 + 1];
    sh[tid] = v;
    __syncthreads();
    for (int off = 128; off > 0; off >>= 1) {
        if (tid < off) sh[tid] += sh[tid + off];
        __syncthreads();
    }
    if (tid == 0) g_tsum[blockIdx.x] = sh[0];
}

__global__ __launch_bounds__(256) void k_scan_b(int E) {
    __shared__ int sh[256];
    int tid = threadIdx.x;
    int v = (tid < NTILES) ? g_tsum[tid] : 0;
    sh[tid] = v;
    __syncthreads();
    for (int off = 1; off < 256; off <<= 1) {
        int t = 0;
        if (tid >= off) t = sh[tid - off];
        __syncthreads();
        sh[tid] += t;
        __syncthreads();
    }
    if (tid < NTILES) g_toff[tid] = sh[tid] - v;   // exclusive
    if (tid == 0) g_coffs[NSEG] = 2 * E;
}

__global__ __launch_bounds__(512) void k_scan_c() {
    __shared__ int sh[512];
    int tid = threadIdx.x;
    int idx = blockIdx.x * TILE + tid;
    int v = (idx < NSEG) ? g_deg[idx] : 0;
    sh[tid] = v;
    __syncthreads();
    for (int off = 1; off < 512; off <<= 1) {
        int t = 0;
        if (tid >= off) t = sh[tid - off];
        __syncthreads();
        sh[tid] += t;
        __syncthreads();
    }
    if (idx < NSEG) {
        int excl = g_toff[blockIdx.x] + sh[tid] - v;
        g_coffs[idx] = excl;
        g_cur[idx] = excl;
    }
}

// ---------------- kernel 4: counting-sort scatter (4 edges/thread) -----------
__global__ __launch_bounds__(256) void k_fill(int E) {
    int e0 = (blockIdx.x * blockDim.x + threadIdx.x) * 4;
    if (e0 >= E) return;
    int2 ht[4];
    int r[4];
#pragma unroll
    for (int k = 0; k < 4; k++) {
        int e = e0 + k;
        if (e < E) { ht[k] = g_ht[e]; r[k] = g_rel32[e]; }
    }
#pragma unroll
    for (int k = 0; k < 4; k++) {
        int e = e0 + k;
        if (e < E) {
            int p1 = atomicAdd(&g_cur[ht[k].x], 1);
            g_elist[p1] = r[k];
            int p2 = atomicAdd(&g_cur[NE + ht[k].y], 1);
            g_elist[p2] = r[k];
        }
    }
}

// ---------------- kernel 5: softmax denominators + aggregation ---------------
// One warp per (side, node). Phase 2 processes 4 edges concurrently using
// 8-lane groups (group = lane>>3, sublane = head = lane&7).
__global__ __launch_bounds__(256) void k_agg(const float* __restrict__ x_r,
                                             float* __restrict__ out) {
    int gw = (blockIdx.x * blockDim.x + threadIdx.x) >> 5;
    int lane = threadIdx.x & 31;
    if (gw >= NSEG) return;
    int side = (gw >= NE) ? 1 : 0;
    int node = side ? (gw - NE) : gw;
    const float* p = side ? g_pt : g_ph;

    int start = g_coffs[gw];
    int end = g_coffs[gw + 1];

    // per-node head scores (vector broadcast loads)
    const float4* pn4 = (const float4*)(p + node * NHEAD);
    float4 pnA = pn4[0], pnB = pn4[1];
    float pn[NHEAD] = {pnA.x, pnA.y, pnA.z, pnA.w, pnB.x, pnB.y, pnB.z, pnB.w};

    // ---- phase 1: denominators per head (no max subtraction: scores ~N(0,2))
    float exs[NHEAD];
#pragma unroll
    for (int h = 0; h < NHEAD; h++) exs[h] = 0.0f;
    for (int j = start + lane; j < end; j += 32) {
        int r = g_elist[j];
        const float4* pr4 = (const float4*)(g_pr + r * NHEAD);
        float4 prA = pr4[0], prB = pr4[1];
        exs[0] += __expf(lrelu(pn[0] + prA.x));
        exs[1] += __expf(lrelu(pn[1] + prA.y));
        exs[2] += __expf(lrelu(pn[2] + prA.z));
        exs[3] += __expf(lrelu(pn[3] + prA.w));
        exs[4] += __expf(lrelu(pn[4] + prB.x));
        exs[5] += __expf(lrelu(pn[5] + prB.y));
        exs[6] += __expf(lrelu(pn[6] + prB.z));
        exs[7] += __expf(lrelu(pn[7] + prB.w));
    }
#pragma unroll
    for (int h = 0; h < NHEAD; h++) {
        float v = exs[h];
#pragma unroll
        for (int off = 16; off > 0; off >>= 1) v += __shfl_xor_sync(0xffffffffu, v, off);
        exs[h] = v;
    }

    // this lane's head (lane&7); avoid dynamic register-array indexing
    int myh = lane & 7;
    int myg = lane >> 3;
    float pn_my = 0.0f, den_my = 0.0f;
#pragma unroll
    for (int h = 0; h < NHEAD; h++) {
        pn_my = (myh == h) ? pn[h] : pn_my;
        den_my = (myh == h) ? exs[h] : den_my;
    }
    float invd_my = 1.0f / (den_my + 1e-16f);

    // ---- phase 2: 4 edges per iteration (one per 8-lane group), unrolled x2
    // acc[k] holds float4 column index (myh + 8k) of the output row.
    float4 acc0 = make_float4(0.f, 0.f, 0.f, 0.f);
    float4 acc1 = acc0, acc2 = acc0, acc3 = acc0;

#define PROC4(BASE)                                                            \
    {                                                                          \
        int j = (BASE) + myg;                                                  \
        bool v = (j < end);                                                    \
        int r = v ? g_elist[j] : 0;                                            \
        float ex = v ? __expf(lrelu(pn_my + g_pr[r * NHEAD + myh])) * invd_my  \
                     : 0.0f;                                                   \
        ex += __shfl_xor_sync(0xffffffffu, ex, 1);                             \
        ex += __shfl_xor_sync(0xffffffffu, ex, 2);                             \
        ex += __shfl_xor_sync(0xffffffffu, ex, 4);                             \
        float a = ex * 0.125f;                                                 \
        const float4* row = (const float4*)(x_r + (long)r * DIM);              \
        float4 v0 = row[myh];                                                  \
        float4 v1 = row[myh + 8];                                              \
        float4 v2 = row[myh + 16];                                             \
        float4 v3 = row[myh + 24];                                             \
        acc0.x += a * v0.x; acc0.y += a * v0.y; acc0.z += a * v0.z; acc0.w += a * v0.w; \
        acc1.x += a * v1.x; acc1.y += a * v1.y; acc1.z += a * v1.z; acc1.w += a * v1.w; \
        acc2.x += a * v2.x; acc2.y += a * v2.y; acc2.z += a * v2.z; acc2.w += a * v2.w; \
        acc3.x += a * v3.x; acc3.y += a * v3.y; acc3.z += a * v3.z; acc3.w += a * v3.w; \
    }

    for (int jb = start; jb < end; jb += 8) {
        PROC4(jb)
        PROC4(jb + 4)
    }
#undef PROC4

    // reduce accumulators across the 4 groups (xor 8, 16)
#define REDACC(A)                                                              \
    A.x += __shfl_xor_sync(0xffffffffu, A.x, 8);                               \
    A.y += __shfl_xor_sync(0xffffffffu, A.y, 8);                               \
    A.z += __shfl_xor_sync(0xffffffffu, A.z, 8);                               \
    A.w += __shfl_xor_sync(0xffffffffu, A.w, 8);                               \
    A.x += __shfl_xor_sync(0xffffffffu, A.x, 16);                              \
    A.y += __shfl_xor_sync(0xffffffffu, A.y, 16);                              \
    A.z += __shfl_xor_sync(0xffffffffu, A.z, 16);                              \
    A.w += __shfl_xor_sync(0xffffffffu, A.w, 16);
    REDACC(acc0) REDACC(acc1) REDACC(acc2) REDACC(acc3)
#undef REDACC

    // lane (g,s) stores acc[g] at float4 index s + 8g == lane -> full 512B store
    float4 res = acc0;
    res = (myg == 1) ? acc1 : res;
    res = (myg == 2) ? acc2 : res;
    res = (myg == 3) ? acc3 : res;
    ((float4*)(out + (long)node * (2 * DIM) + side * DIM))[lane] = res;
}

// ---------------- launch ------------------------------------------------------
extern "C" void kernel_launch(void* const* d_in, const int* in_sizes, int n_in,
                              void* d_out, int out_size) {
    const float* x_e = (const float*)d_in[0];
    const float* x_r = (const float*)d_in[1];
    const float* Wh  = (const float*)d_in[2];
    const float* Wt  = (const float*)d_in[3];
    const float* Wr  = (const float*)d_in[4];
    const void*  ei  = d_in[5];
    const void*  rel = d_in[6];
    int E = in_sizes[6];          // element count of rel == number of edges

    k_zero_detect<<<(NSEG + 255) / 256, 256>>>((const unsigned*)ei);

    k_proj<<<(NE * 32 + 255) / 256, 256>>>(x_e, Wh, Wt, NE, 0);
    k_proj<<<(NR * 32 + 255) / 256, 256>>>(x_r, Wr, nullptr, NR, 1);

    int tE4 = (E + 3) / 4;
    k_hist<<<(tE4 + 255) / 256, 256>>>(ei, rel, E);

    k_scan_a<<<NTILES, 256>>>();
    k_scan_b<<<1, 256>>>(E);
    k_scan_c<<<NTILES, 512>>>();

    k_fill<<<(tE4 + 255) / 256, 256>>>(E);

    k_agg<<<(NSEG * 32 + 255) / 256, 256>>>(x_r, (float*)d_out);
}

// round 4
// speedup vs baseline: 1.0674x; 1.0674x over previous
#include <cuda_runtime.h>
#include <cuda_bf16.h>
#include <cstdint>

// Problem constants (fixed by the dataset)
#define NE 50000
#define NR 2000
#define EMAX 800000
#define NHEAD 8
#define DIM 128
#define NEG_SLOPE 0.01f
#define NSEG (2 * NE)
#define TILE 512
#define NTILES ((NSEG + TILE - 1) / TILE)   // 196

// ---------------- scratch (static device globals; no allocation) -------------
__device__ float g_ph[NE * NHEAD];      // x_e @ Wh.T
__device__ float g_pt[NE * NHEAD];      // x_e @ Wt.T
__device__ float g_pr[NR * NHEAD];      // x_r @ Wr.T
__device__ int   g_deg[NSEG];           // degrees: [0,NE)=h side, [NE,2NE)=t side
__device__ int   g_coffs[NSEG + 1];     // exclusive offsets (combined h|t CSR)
__device__ int   g_cur[NSEG];           // scatter cursors
__device__ int   g_elist[2 * EMAX];     // rel id per slot, grouped by (side,node)
__device__ int2  g_ht[EMAX];            // decoded (h, t) per edge
__device__ int   g_rel32[EMAX];         // rel cast to int32
__device__ int   g_tsum[NTILES];        // per-tile degree sums
__device__ int   g_toff[NTILES];        // per-tile exclusive offsets
__device__ int   g_is64;                // 1 if edge_index/rel are int64

__device__ __forceinline__ float lrelu(float s) {
    return (s > 0.0f) ? s : NEG_SLOPE * s;
}

// ---------------- kernel 0: zero degrees + detect index width ----------------
__global__ void k_zero_detect(const unsigned* ei_words) {
    int i = blockIdx.x * blockDim.x + threadIdx.x;
    if (i < NSEG) g_deg[i] = 0;
    if (blockIdx.x == 0 && threadIdx.x < 32) {
        unsigned w = ei_words[2 * threadIdx.x + 1];
        unsigned ball = __ballot_sync(0xffffffffu, w == 0u);
        if (threadIdx.x == 0) g_is64 = (ball == 0xffffffffu) ? 1 : 0;
    }
}

// ---------------- kernel 1: projections (warp per row) -----------------------
__global__ __launch_bounds__(256) void k_proj(const float* __restrict__ x,
                                              const float* __restrict__ Wa,
                                              const float* __restrict__ Wb,
                                              int n, int mode) {
    int w = (blockIdx.x * blockDim.x + threadIdx.x) >> 5;
    int lane = threadIdx.x & 31;
    if (w >= n) return;
    float* pa = (mode == 0) ? g_ph : g_pr;
    float* pb = (mode == 0) ? g_pt : nullptr;

    const float* xr = x + (long)w * DIM;
    float x0 = xr[lane], x1 = xr[lane + 32], x2 = xr[lane + 64], x3 = xr[lane + 96];

#pragma unroll
    for (int h = 0; h < NHEAD; h++) {
        const float* wa = Wa + h * DIM;
        float a = x0 * wa[lane] + x1 * wa[lane + 32] + x2 * wa[lane + 64] + x3 * wa[lane + 96];
#pragma unroll
        for (int off = 16; off > 0; off >>= 1) a += __shfl_xor_sync(0xffffffffu, a, off);
        if (lane == 0) pa[w * NHEAD + h] = a;
        if (pb) {
            const float* wb = Wb + h * DIM;
            float b = x0 * wb[lane] + x1 * wb[lane + 32] + x2 * wb[lane + 64] + x3 * wb[lane + 96];
#pragma unroll
            for (int off = 16; off > 0; off >>= 1) b += __shfl_xor_sync(0xffffffffu, b, off);
            if (lane == 0) pb[w * NHEAD + h] = b;
        }
    }
}

// ---------------- kernel 2: decode + degree histogram (1 edge/thread) --------
__global__ __launch_bounds__(256) void k_hist(const void* __restrict__ ei,
                                              const void* __restrict__ rel, int E) {
    int e = blockIdx.x * blockDim.x + threadIdx.x;
    if (e >= E) return;
    int is64 = g_is64;
    int h, t, r;
    if (is64) {
        h = (int)((const long long*)ei)[e];
        t = (int)((const long long*)ei)[(long)E + e];
        r = (int)((const long long*)rel)[e];
    } else {
        h = ((const int*)ei)[e];
        t = ((const int*)ei)[(long)E + e];
        r = ((const int*)rel)[e];
    }
    g_ht[e] = make_int2(h, t);
    g_rel32[e] = r;
    atomicAdd(&g_deg[h], 1);
    atomicAdd(&g_deg[NE + t], 1);
}

// ---------------- kernels 3a/3b/3c: parallel exclusive scan ------------------
__global__ __launch_bounds__(256) void k_scan_a() {
    __shared__ int sh[256];
    int tid = threadIdx.x;
    int i0 = blockIdx.x * TILE + tid * 2;
    int v = 0;
    if (i0 < NSEG) v += g_deg[i0];
    if (i0 + 1 < NSEG) v += g_deg[i0 + 1];
    sh[tid] = v;
    __syncthreads();
    for (int off = 128; off > 0; off >>= 1) {
        if (tid < off) sh[tid] += sh[tid + off];
        __syncthreads();
    }
    if (tid == 0) g_tsum[blockIdx.x] = sh[0];
}

__global__ __launch_bounds__(256) void k_scan_b(int E) {
    __shared__ int sh[256];
    int tid = threadIdx.x;
    int v = (tid < NTILES) ? g_tsum[tid] : 0;
    sh[tid] = v;
    __syncthreads();
    for (int off = 1; off < 256; off <<= 1) {
        int t = 0;
        if (tid >= off) t = sh[tid - off];
        __syncthreads();
        sh[tid] += t;
        __syncthreads();
    }
    if (tid < NTILES) g_toff[tid] = sh[tid] - v;   // exclusive
    if (tid == 0) g_coffs[NSEG] = 2 * E;
}

__global__ __launch_bounds__(512) void k_scan_c() {
    __shared__ int sh[512];
    int tid = threadIdx.x;
    int idx = blockIdx.x * TILE + tid;
    int v = (idx < NSEG) ? g_deg[idx] : 0;
    sh[tid] = v;
    __syncthreads();
    for (int off = 1; off < 512; off <<= 1) {
        int t = 0;
        if (tid >= off) t = sh[tid - off];
        __syncthreads();
        sh[tid] += t;
        __syncthreads();
    }
    if (idx < NSEG) {
        int excl = g_toff[blockIdx.x] + sh[tid] - v;
        g_coffs[idx] = excl;
        g_cur[idx] = excl;
    }
}

// ---------------- kernel 4: counting-sort scatter (1 edge/thread) ------------
__global__ __launch_bounds__(256) void k_fill(int E) {
    int e = blockIdx.x * blockDim.x + threadIdx.x;
    if (e >= E) return;
    int2 ht = g_ht[e];
    int r = g_rel32[e];
    int p1 = atomicAdd(&g_cur[ht.x], 1);
    g_elist[p1] = r;
    int p2 = atomicAdd(&g_cur[NE + ht.y], 1);
    g_elist[p2] = r;
}

// ---------------- kernel 5: softmax denominators + aggregation ---------------
// One warp per (side, node). Phase 2: 4 edges concurrently via 8-lane groups
// (group = lane>>3, head = lane&7); no predicated dummy gathers; whole-warp
// tail loop for the last deg%4 edges.
__global__ __launch_bounds__(256) void k_agg(const float* __restrict__ x_r,
                                             float* __restrict__ out) {
    int gw = (blockIdx.x * blockDim.x + threadIdx.x) >> 5;
    int lane = threadIdx.x & 31;
    if (gw >= NSEG) return;
    int side = (gw >= NE) ? 1 : 0;
    int node = side ? (gw - NE) : gw;
    const float* p = side ? g_pt : g_ph;

    int start = g_coffs[gw];
    int end = g_coffs[gw + 1];

    // per-node head scores (vector broadcast loads)
    const float4* pn4 = (const float4*)(p + node * NHEAD);
    float4 pnA = pn4[0], pnB = pn4[1];
    float pn[NHEAD] = {pnA.x, pnA.y, pnA.z, pnA.w, pnB.x, pnB.y, pnB.z, pnB.w};

    // ---- phase 1: denominators per head (no max subtraction: scores ~N(0,2))
    float exs[NHEAD];
#pragma unroll
    for (int h = 0; h < NHEAD; h++) exs[h] = 0.0f;
    for (int j = start + lane; j < end; j += 32) {
        int r = g_elist[j];
        const float4* pr4 = (const float4*)(g_pr + r * NHEAD);
        float4 prA = pr4[0], prB = pr4[1];
        exs[0] += __expf(lrelu(pn[0] + prA.x));
        exs[1] += __expf(lrelu(pn[1] + prA.y));
        exs[2] += __expf(lrelu(pn[2] + prA.z));
        exs[3] += __expf(lrelu(pn[3] + prA.w));
        exs[4] += __expf(lrelu(pn[4] + prB.x));
        exs[5] += __expf(lrelu(pn[5] + prB.y));
        exs[6] += __expf(lrelu(pn[6] + prB.z));
        exs[7] += __expf(lrelu(pn[7] + prB.w));
    }
#pragma unroll
    for (int h = 0; h < NHEAD; h++) {
        float v = exs[h];
#pragma unroll
        for (int off = 16; off > 0; off >>= 1) v += __shfl_xor_sync(0xffffffffu, v, off);
        exs[h] = v;
    }

    int myh = lane & 7;
    int myg = lane >> 3;
    float pn_my = 0.0f, den_my = 0.0f;
#pragma unroll
    for (int h = 0; h < NHEAD; h++) {
        pn_my = (myh == h) ? pn[h] : pn_my;
        den_my = (myh == h) ? exs[h] : den_my;
    }
    float invd_my = 1.0f / (den_my + 1e-16f);

    // ---- phase 2 ----
    float4 acc0 = make_float4(0.f, 0.f, 0.f, 0.f);
    float4 acc1 = acc0, acc2 = acc0, acc3 = acc0;

#define PROC4(BASE)                                                            \
    {                                                                          \
        int r = g_elist[(BASE) + myg];                                         \
        float ex = __expf(lrelu(pn_my + g_pr[r * NHEAD + myh])) * invd_my;     \
        ex += __shfl_xor_sync(0xffffffffu, ex, 1);                             \
        ex += __shfl_xor_sync(0xffffffffu, ex, 2);                             \
        ex += __shfl_xor_sync(0xffffffffu, ex, 4);                             \
        float a = ex * 0.125f;                                                 \
        const float4* row = (const float4*)(x_r + (long)r * DIM);              \
        float4 v0 = row[myh];                                                  \
        float4 v1 = row[myh + 8];                                              \
        float4 v2 = row[myh + 16];                                             \
        float4 v3 = row[myh + 24];                                             \
        acc0.x += a * v0.x; acc0.y += a * v0.y; acc0.z += a * v0.z; acc0.w += a * v0.w; \
        acc1.x += a * v1.x; acc1.y += a * v1.y; acc1.z += a * v1.z; acc1.w += a * v1.w; \
        acc2.x += a * v2.x; acc2.y += a * v2.y; acc2.z += a * v2.z; acc2.w += a * v2.w; \
        acc3.x += a * v3.x; acc3.y += a * v3.y; acc3.z += a * v3.z; acc3.w += a * v3.w; \
    }

    int jb = start;
    for (; jb + 8 <= end; jb += 8) {
        PROC4(jb)
        PROC4(jb + 4)
    }
    if (jb + 4 <= end) {
        PROC4(jb)
        jb += 4;
    }
#undef PROC4

    // reduce accumulators across the 4 groups (xor 8, 16)
#define REDACC(A)                                                              \
    A.x += __shfl_xor_sync(0xffffffffu, A.x, 8);                               \
    A.y += __shfl_xor_sync(0xffffffffu, A.y, 8);                               \
    A.z += __shfl_xor_sync(0xffffffffu, A.z, 8);                               \
    A.w += __shfl_xor_sync(0xffffffffu, A.w, 8);                               \
    A.x += __shfl_xor_sync(0xffffffffu, A.x, 16);                              \
    A.y += __shfl_xor_sync(0xffffffffu, A.y, 16);                              \
    A.z += __shfl_xor_sync(0xffffffffu, A.z, 16);                              \
    A.w += __shfl_xor_sync(0xffffffffu, A.w, 16);
    REDACC(acc0) REDACC(acc1) REDACC(acc2) REDACC(acc3)
#undef REDACC

    // lane (g,s) owns float4 column s + 8g == lane
    float4 res = acc0;
    res = (myg == 1) ? acc1 : res;
    res = (myg == 2) ? acc2 : res;
    res = (myg == 3) ? acc3 : res;

    // whole-warp tail (0..3 edges): each lane loads its own column directly
    for (; jb < end; jb++) {
        int r = g_elist[jb];                      // uniform -> broadcast
        float ex = __expf(lrelu(pn_my + g_pr[r * NHEAD + myh])) * invd_my;
        ex += __shfl_xor_sync(0xffffffffu, ex, 1);
        ex += __shfl_xor_sync(0xffffffffu, ex, 2);
        ex += __shfl_xor_sync(0xffffffffu, ex, 4);
        float a = ex * 0.125f;
        float4 v = ((const float4*)(x_r + (long)r * DIM))[lane];
        res.x += a * v.x;
        res.y += a * v.y;
        res.z += a * v.z;
        res.w += a * v.w;
    }

    // streaming store: don't let the 51MB output evict hot x_r/pr/elist from L2
    __stcs((float4*)(out + (long)node * (2 * DIM) + side * DIM) + lane, res);
}

// ---------------- launch ------------------------------------------------------
extern "C" void kernel_launch(void* const* d_in, const int* in_sizes, int n_in,
                              void* d_out, int out_size) {
    const float* x_e = (const float*)d_in[0];
    const float* x_r = (const float*)d_in[1];
    const float* Wh  = (const float*)d_in[2];
    const float* Wt  = (const float*)d_in[3];
    const float* Wr  = (const float*)d_in[4];
    const void*  ei  = d_in[5];
    const void*  rel = d_in[6];
    int E = in_sizes[6];          // element count of rel == number of edges

    k_zero_detect<<<(NSEG + 255) / 256, 256>>>((const unsigned*)ei);

    k_proj<<<(NE * 32 + 255) / 256, 256>>>(x_e, Wh, Wt, NE, 0);
    k_proj<<<(NR * 32 + 255) / 256, 256>>>(x_r, Wr, nullptr, NR, 1);

    k_hist<<<(E + 255) / 256, 256>>>(ei, rel, E);

    k_scan_a<<<NTILES, 256>>>();
    k_scan_b<<<1, 256>>>(E);
    k_scan_c<<<NTILES, 512>>>();

    k_fill<<<(E + 255) / 256, 256>>>(E);

    k_agg<<<(NSEG * 32 + 255) / 256, 256>>>(x_r, (float*)d_out);
}